// round 5
// baseline (speedup 1.0000x reference)
#include <cuda_runtime.h>
#include <cstdint>

// ---- problem constants (match reference) ----
#define BB 4
#define HH 128
#define WW 128
#define SS 72
#define SPS 24          // slices per stack
#define ZS 120          // z_scale
#define ZV 122          // padded depth
#define ST_RATIO 5.0f

#define VOXELS (BB * HH * WW * ZV)      // 7,995,392
#define PIXELS (BB * HH * WW * SS)      // 4,718,592
#define OUT_PER (BB * HH * WW * ZS)     // 7,864,320
#define HWSZ   (HH * WW)                // 16384

// Interleaved scratch: [2*lin]=N, [2*lin+1]=D. 64 MB, L2-resident.
// Zero-initialized at module load; finalize restores the all-zero invariant
// after every execution, so no memset is needed.
__device__ __align__(16) float g_acc[2 * VOXELS];

__device__ __forceinline__ void red_add_v2(float* p, float a, float b) {
    asm volatile("red.global.add.v2.f32 [%0], {%1, %2};"
                 :: "l"(p), "f"(a), "f"(b) : "memory");
}

// ---------------------------------------------------------------------------
// Merged-pair emit along the warp-varying merge axis.
// Lane l absorbs lane l-1's high-corner contribution iff the addresses are
// exactly equal (sum-preserving regardless of clipping). All lanes converged.
// ---------------------------------------------------------------------------
__device__ __forceinline__ void emit_pair(int lane, int lo_lin, int hi_lin,
                                          float wlo, float whi, float v)
{
    float Nhi = whi * v;
    float nbN = __shfl_up_sync(0xffffffffu, Nhi, 1);
    float nbD = __shfl_up_sync(0xffffffffu, whi, 1);
    int   nbL = __shfl_up_sync(0xffffffffu, hi_lin, 1);

    bool mrg = (lane > 0) && (nbL == lo_lin);
    unsigned bal = __ballot_sync(0xffffffffu, mrg);
    bool absorbed = (bal & (2u << lane)) != 0u;   // lane 31: (2u<<31)==0 -> false

    float addN = mrg ? nbN : 0.0f;
    float addD = mrg ? nbD : 0.0f;

    red_add_v2(&g_acc[2 * lo_lin], wlo * v + addN, wlo + addD);
    if (!absorbed)
        red_add_v2(&g_acc[2 * hi_lin], Nhi, whi);
}

// ---------------------------------------------------------------------------
// Splat: warp lanes span w; (b,h,s) warp-uniform (=> orientation warp-uniform).
// Block = 8 warps covering 8 consecutive slices for the same (b, h, w-chunk).
// vol is read directly (no transpose kernel) via a smem staging tile:
// the staging load maps threads to 4w x 8s -> 4 fully-used 32B sectors per
// warp; the tile is padded (stride 9) so the lane->w readback is conflict-free.
// Grid = B * 9 * H * 4 = 18432 blocks of 256.
// ---------------------------------------------------------------------------
__global__ __launch_bounds__(256) void splat_kernel(
    const float* __restrict__ vol,    // (B,H,W,S,1)
    const float* __restrict__ trf)    // (B,S,3,4)
{
    __shared__ float sv[32 * 9];      // [w_local * 9 + s_local]

    int tid  = threadIdx.x;
    int lane = tid & 31;
    int wid  = tid >> 5;
    int blk  = blockIdx.x;

    int wc = blk & 3;                 // w chunk (0..3)
    int h  = (blk >> 2) & 127;
    int sc = (blk >> 9) % 9;          // s chunk (0..8)
    int b  = blk / 4608;

    // Stage vol[b, h, wc*32 .. +31, sc*8 .. +7] into smem.
    {
        int wl = tid >> 3;            // 0..31
        int sl = tid & 7;             // 0..7
        const float* src = vol + (((size_t)(b * HH + h) * WW + wc * 32) * SS
                                  + sc * 8);
        sv[wl * 9 + sl] = src[wl * SS + sl];
    }
    __syncthreads();

    int s = sc * 8 + wid;             // warp-uniform
    int w = wc * 32 + lane;

    float v = sv[lane * 9 + wid];     // conflict-free (stride 9)

    const float* Ap = trf + (size_t)(b * SS + s) * 12;
    float A00 = Ap[0] + 1.0f, A01 = Ap[1],        A02 = Ap[2],         A03 = Ap[3];
    float A10 = Ap[4],        A11 = Ap[5] + 1.0f, A12 = Ap[6],         A13 = Ap[7];
    float A20 = Ap[8],        A21 = Ap[9],        A22 = Ap[10] + 1.0f, A23 = Ap[11];

    int o = s / SPS;                  // 0=axi, 1=cor, 2=sag  (warp-uniform)
    float t = (float)(s % SPS) * ST_RATIO;

    float bx, by, bz;
    if (o == 0)      { bx = (float)h; by = (float)w; bz = t; }
    else if (o == 1) { bx = (float)h; by = t;        bz = (float)w; }
    else             { bx = t;        by = (float)h; bz = (float)w; }

    float x = A00 * bx + A01 * by + A02 * bz + A03;
    float y = A10 * bx + A11 * by + A12 * bz + A13;
    float z = A20 * bx + A21 * by + A22 * bz + A23 + 1.0f;

    float x0f = floorf(x), y0f = floorf(y), z0f = floorf(z);
    float wx = x - x0f, wy = y - y0f, wz = z - z0f;
    int x0 = (int)x0f, y0 = (int)y0f, z0 = (int)z0f;

    // clipped indices + validity masks (as weights)
    int cx0 = min(max(x0,     0), HH - 1);
    int cx1 = min(max(x0 + 1, 0), HH - 1);
    int cy0 = min(max(y0,     0), WW - 1);
    int cy1 = min(max(y0 + 1, 0), WW - 1);
    int cz0 = min(max(z0,     0), ZV - 1);
    int cz1 = min(max(z0 + 1, 0), ZV - 1);
    float vx0 = (x0 >= 0 && x0 < HH)         ? 1.0f : 0.0f;
    float vx1 = (x0 + 1 >= 0 && x0 + 1 < HH) ? 1.0f : 0.0f;
    float vy0 = (y0 >= 0 && y0 < WW)         ? 1.0f : 0.0f;
    float vy1 = (y0 + 1 >= 0 && y0 + 1 < WW) ? 1.0f : 0.0f;
    float vz0 = (z0 >= 0 && z0 < ZV)         ? 1.0f : 0.0f;
    float vz1 = (z0 + 1 >= 0 && z0 + 1 < ZV) ? 1.0f : 0.0f;

    float fx0 = (1.0f - wx) * vx0, fx1 = wx * vx1;
    float fy0 = (1.0f - wy) * vy0, fy1 = wy * vy1;
    float fz0 = (1.0f - wz) * vz0, fz1 = wz * vz1;

    int base_b = b * HH;

    if (o == 0) {
        // axi: y varies with lane -> merge along y (address delta = ZV)
        #pragma unroll
        for (int dx = 0; dx < 2; dx++) {
            int   cx  = dx ? cx1 : cx0;
            float fxm = dx ? fx1 : fx0;
            int row = (base_b + cx) * WW;
            #pragma unroll
            for (int dz = 0; dz < 2; dz++) {
                int   cz  = dz ? cz1 : cz0;
                float fxz = fxm * (dz ? fz1 : fz0);
                int lo_lin = (row + cy0) * ZV + cz;
                int hi_lin = (row + cy1) * ZV + cz;
                emit_pair(lane, lo_lin, hi_lin, fxz * fy0, fxz * fy1, v);
            }
        }
    } else {
        // cor/sag: z varies with lane -> merge along z (address delta = 1)
        #pragma unroll
        for (int dx = 0; dx < 2; dx++) {
            int   cx  = dx ? cx1 : cx0;
            float fxm = dx ? fx1 : fx0;
            int row = (base_b + cx) * WW;
            #pragma unroll
            for (int dy = 0; dy < 2; dy++) {
                int   cy  = dy ? cy1 : cy0;
                float fxy = fxm * (dy ? fy1 : fy0);
                int lin_xy = (row + cy) * ZV;
                emit_pair(lane, lin_xy + cz0, lin_xy + cz1, fxy * fz0, fxy * fz1, v);
            }
        }
    }
}

// ---------------------------------------------------------------------------
// Finalize: crop z[1:1+ZS], split interleaved N/D, where(D<=0, 1, D),
// AND re-zero every accumulator pair (replaces the memset for the next run).
// One thread handles 4 consecutive z values -> float4 output stores.
// Threads with zq==0 also zero the two z-pads (zoff 0 and 121).
// ---------------------------------------------------------------------------
__global__ __launch_bounds__(256) void finalize_kernel(float* __restrict__ out)
{
    int j = blockIdx.x * blockDim.x + threadIdx.x;   // 65536 * 30 threads
    int zq  = j % 30;
    int hwb = j / 30;

    int z0 = zq * 4;                       // output z base (0..116)
    int lin = hwb * ZV + z0 + 1;           // accumulator z offset (1..117)

    float2* acc = reinterpret_cast<float2*>(g_acc);
    float2 p0 = acc[lin];
    float2 p1 = acc[lin + 1];
    float2 p2 = acc[lin + 2];
    float2 p3 = acc[lin + 3];

    const float2 zz = make_float2(0.0f, 0.0f);
    acc[lin]     = zz;
    acc[lin + 1] = zz;
    acc[lin + 2] = zz;
    acc[lin + 3] = zz;
    if (zq == 0) {
        acc[hwb * ZV]       = zz;          // pad z = 0
        acc[hwb * ZV + 121] = zz;          // pad z = 121
    }

    int oj = hwb * ZS + z0;
    float4 nv = make_float4(p0.x, p1.x, p2.x, p3.x);
    float4 dv = make_float4(p0.y > 0.0f ? p0.y : 1.0f,
                            p1.y > 0.0f ? p1.y : 1.0f,
                            p2.y > 0.0f ? p2.y : 1.0f,
                            p3.y > 0.0f ? p3.y : 1.0f);
    *reinterpret_cast<float4*>(&out[oj])           = nv;
    *reinterpret_cast<float4*>(&out[OUT_PER + oj]) = dv;
}

// ---------------------------------------------------------------------------
extern "C" void kernel_launch(void* const* d_in, const int* in_sizes, int n_in,
                              void* d_out, int out_size)
{
    const float* vol = (const float*)d_in[0];
    const float* trf = (const float*)d_in[1];
    float* out = (float*)d_out;

    splat_kernel<<<BB * 9 * HH * 4, 256>>>(vol, trf);
    finalize_kernel<<<(HWSZ * BB * 30) / 256, 256>>>(out);
}

// round 6
// speedup vs baseline: 1.6656x; 1.6656x over previous
#include <cuda_runtime.h>
#include <cstdint>

// ---- problem constants (match reference) ----
#define BB 4
#define HH 128
#define WW 128
#define SS 72
#define SPS 24          // slices per stack
#define ZS 120          // z_scale
#define ZV 122          // padded depth
#define ST_RATIO 5.0f

#define VOXELS (BB * HH * WW * ZV)      // 7,995,392
#define PIXELS (BB * HH * WW * SS)      // 4,718,592
#define OUT_PER (BB * HH * WW * ZS)     // 7,864,320
#define HWSZ   (HH * WW)                // 16384

// Interleaved scratch: [2*lin]=N, [2*lin+1]=D. 64 MB, L2-resident.
// Zero before each splat: a tail cudaMemsetAsync restores the invariant at
// the end of every execution (and leaves the zeroed lines warm in L2).
__device__ __align__(16) float g_acc[2 * VOXELS];

__device__ __forceinline__ void red_add_v2(float* p, float a, float b) {
    asm volatile("red.global.add.v2.f32 [%0], {%1, %2};"
                 :: "l"(p), "f"(a), "f"(b) : "memory");
}

// ---------------------------------------------------------------------------
// Merged-pair emit along the warp-varying merge axis.
// Lane l absorbs lane l-1's high-corner contribution iff the addresses are
// exactly equal (sum-preserving regardless of clipping). All lanes converged.
// ---------------------------------------------------------------------------
__device__ __forceinline__ void emit_pair(int lane, int lo_lin, int hi_lin,
                                          float wlo, float whi, float v)
{
    float Nhi = whi * v;
    float nbN = __shfl_up_sync(0xffffffffu, Nhi, 1);
    float nbD = __shfl_up_sync(0xffffffffu, whi, 1);
    int   nbL = __shfl_up_sync(0xffffffffu, hi_lin, 1);

    bool mrg = (lane > 0) && (nbL == lo_lin);
    unsigned bal = __ballot_sync(0xffffffffu, mrg);
    bool absorbed = (bal & (2u << lane)) != 0u;   // lane 31: (2u<<31)==0 -> false

    float addN = mrg ? nbN : 0.0f;
    float addD = mrg ? nbD : 0.0f;

    red_add_v2(&g_acc[2 * lo_lin], wlo * v + addN, wlo + addD);
    if (!absorbed)
        red_add_v2(&g_acc[2 * hi_lin], Nhi, whi);
}

// ---------------------------------------------------------------------------
// Splat: warp lanes span w; (b,h,s) warp-uniform (=> orientation warp-uniform).
// Block = 8 warps covering 8 consecutive slices for the same (b, h, w-chunk).
// vol read staged through a padded smem tile (coalesced load, conflict-free
// readback). Grid = B * 9 * H * 4 = 18432 blocks of 256.
// ---------------------------------------------------------------------------
__global__ __launch_bounds__(256) void splat_kernel(
    const float* __restrict__ vol,    // (B,H,W,S,1)
    const float* __restrict__ trf)    // (B,S,3,4)
{
    __shared__ float sv[32 * 9];      // [w_local * 9 + s_local]

    int tid  = threadIdx.x;
    int lane = tid & 31;
    int wid  = tid >> 5;
    int blk  = blockIdx.x;

    int wc = blk & 3;                 // w chunk (0..3)
    int h  = (blk >> 2) & 127;
    int sc = (blk >> 9) % 9;          // s chunk (0..8)
    int b  = blk / 4608;

    // Stage vol[b, h, wc*32 .. +31, sc*8 .. +7] into smem.
    {
        int wl = tid >> 3;            // 0..31
        int sl = tid & 7;             // 0..7
        const float* src = vol + (((size_t)(b * HH + h) * WW + wc * 32) * SS
                                  + sc * 8);
        sv[wl * 9 + sl] = src[wl * SS + sl];
    }
    __syncthreads();

    int s = sc * 8 + wid;             // warp-uniform
    int w = wc * 32 + lane;

    float v = sv[lane * 9 + wid];     // conflict-free (stride 9)

    const float* Ap = trf + (size_t)(b * SS + s) * 12;
    float A00 = Ap[0] + 1.0f, A01 = Ap[1],        A02 = Ap[2],         A03 = Ap[3];
    float A10 = Ap[4],        A11 = Ap[5] + 1.0f, A12 = Ap[6],         A13 = Ap[7];
    float A20 = Ap[8],        A21 = Ap[9],        A22 = Ap[10] + 1.0f, A23 = Ap[11];

    int o = s / SPS;                  // 0=axi, 1=cor, 2=sag  (warp-uniform)
    float t = (float)(s % SPS) * ST_RATIO;

    float bx, by, bz;
    if (o == 0)      { bx = (float)h; by = (float)w; bz = t; }
    else if (o == 1) { bx = (float)h; by = t;        bz = (float)w; }
    else             { bx = t;        by = (float)h; bz = (float)w; }

    float x = A00 * bx + A01 * by + A02 * bz + A03;
    float y = A10 * bx + A11 * by + A12 * bz + A13;
    float z = A20 * bx + A21 * by + A22 * bz + A23 + 1.0f;

    float x0f = floorf(x), y0f = floorf(y), z0f = floorf(z);
    float wx = x - x0f, wy = y - y0f, wz = z - z0f;
    int x0 = (int)x0f, y0 = (int)y0f, z0 = (int)z0f;

    // clipped indices + validity masks (as weights)
    int cx0 = min(max(x0,     0), HH - 1);
    int cx1 = min(max(x0 + 1, 0), HH - 1);
    int cy0 = min(max(y0,     0), WW - 1);
    int cy1 = min(max(y0 + 1, 0), WW - 1);
    int cz0 = min(max(z0,     0), ZV - 1);
    int cz1 = min(max(z0 + 1, 0), ZV - 1);
    float vx0 = (x0 >= 0 && x0 < HH)         ? 1.0f : 0.0f;
    float vx1 = (x0 + 1 >= 0 && x0 + 1 < HH) ? 1.0f : 0.0f;
    float vy0 = (y0 >= 0 && y0 < WW)         ? 1.0f : 0.0f;
    float vy1 = (y0 + 1 >= 0 && y0 + 1 < WW) ? 1.0f : 0.0f;
    float vz0 = (z0 >= 0 && z0 < ZV)         ? 1.0f : 0.0f;
    float vz1 = (z0 + 1 >= 0 && z0 + 1 < ZV) ? 1.0f : 0.0f;

    float fx0 = (1.0f - wx) * vx0, fx1 = wx * vx1;
    float fy0 = (1.0f - wy) * vy0, fy1 = wy * vy1;
    float fz0 = (1.0f - wz) * vz0, fz1 = wz * vz1;

    int base_b = b * HH;

    if (o == 0) {
        // axi: y varies with lane -> merge along y (address delta = ZV)
        #pragma unroll
        for (int dx = 0; dx < 2; dx++) {
            int   cx  = dx ? cx1 : cx0;
            float fxm = dx ? fx1 : fx0;
            int row = (base_b + cx) * WW;
            #pragma unroll
            for (int dz = 0; dz < 2; dz++) {
                int   cz  = dz ? cz1 : cz0;
                float fxz = fxm * (dz ? fz1 : fz0);
                int lo_lin = (row + cy0) * ZV + cz;
                int hi_lin = (row + cy1) * ZV + cz;
                emit_pair(lane, lo_lin, hi_lin, fxz * fy0, fxz * fy1, v);
            }
        }
    } else {
        // cor/sag: z varies with lane -> merge along z (address delta = 1)
        #pragma unroll
        for (int dx = 0; dx < 2; dx++) {
            int   cx  = dx ? cx1 : cx0;
            float fxm = dx ? fx1 : fx0;
            int row = (base_b + cx) * WW;
            #pragma unroll
            for (int dy = 0; dy < 2; dy++) {
                int   cy  = dy ? cy1 : cy0;
                float fxy = fxm * (dy ? fy1 : fy0);
                int lin_xy = (row + cy) * ZV;
                emit_pair(lane, lin_xy + cz0, lin_xy + cz1, fxy * fz0, fxy * fz1, v);
            }
        }
    }
}

// ---------------------------------------------------------------------------
// Finalize: crop z[1:1+ZS], split interleaved N/D, where(D<=0, 1, D).
// Coalesced mapping (consecutive threads -> consecutive z) with ILP=2:
// each thread handles z and z+60 of the same (b,h,w) column.
// ---------------------------------------------------------------------------
__global__ __launch_bounds__(256) void finalize_kernel(float* __restrict__ out)
{
    int j = blockIdx.x * blockDim.x + threadIdx.x;   // OUT_PER/2 threads
    int z   = j % 60;
    int hwb = j / 60;

    const float2* acc = reinterpret_cast<const float2*>(g_acc);
    int lin = hwb * ZV + z + 1;
    float2 pa = acc[lin];
    float2 pb = acc[lin + 60];

    int oj = hwb * ZS + z;
    out[oj]                 = pa.x;
    out[oj + 60]            = pb.x;
    out[OUT_PER + oj]       = (pa.y > 0.0f) ? pa.y : 1.0f;
    out[OUT_PER + oj + 60]  = (pb.y > 0.0f) ? pb.y : 1.0f;
}

// ---------------------------------------------------------------------------
extern "C" void kernel_launch(void* const* d_in, const int* in_sizes, int n_in,
                              void* d_out, int out_size)
{
    const float* vol = (const float*)d_in[0];
    const float* trf = (const float*)d_in[1];
    float* out = (float*)d_out;

    splat_kernel<<<BB * 9 * HH * 4, 256>>>(vol, trf);
    finalize_kernel<<<(OUT_PER / 2) / 256, 256>>>(out);

    // Restore the all-zero invariant for the next replay; also leaves the
    // accumulator zeroed and warm in L2 for the next splat.
    void* acc_ptr = nullptr;
    cudaGetSymbolAddress(&acc_ptr, g_acc);
    cudaMemsetAsync(acc_ptr, 0, sizeof(float) * 2 * VOXELS, 0);
}

// round 7
// speedup vs baseline: 1.6704x; 1.0029x over previous
#include <cuda_runtime.h>
#include <cstdint>

// ---- problem constants (match reference) ----
#define BB 4
#define HH 128
#define WW 128
#define SS 72
#define SPS 24          // slices per stack
#define ZS 120          // z_scale
#define ZV 122          // padded depth
#define ST_RATIO 5.0f

#define VOXELS (BB * HH * WW * ZV)      // 7,995,392
#define PIXELS (BB * HH * WW * SS)      // 4,718,592
#define OUT_PER (BB * HH * WW * ZS)     // 7,864,320
#define HWSZ   (HH * WW)                // 16384

// Interleaved scratch: [2*lin]=N, [2*lin+1]=D. 64 MB, L2-resident.
// Zero before each splat: a tail cudaMemsetAsync restores the invariant at
// the end of every execution (and leaves the zeroed lines warm in L2).
__device__ __align__(16) float g_acc[2 * VOXELS];

__device__ __forceinline__ void red_add_v2(float* p, float a, float b) {
    asm volatile("red.global.add.v2.f32 [%0], {%1, %2};"
                 :: "l"(p), "f"(a), "f"(b) : "memory");
}

// ---------------------------------------------------------------------------
// Merged-pair emit along the warp-varying merge axis.
// Lane l absorbs lane l-1's high-corner contribution iff the addresses are
// exactly equal (sum-preserving regardless of clipping). All lanes converged.
// ---------------------------------------------------------------------------
__device__ __forceinline__ void emit_pair(int lane, int lo_lin, int hi_lin,
                                          float wlo, float whi, float v)
{
    float Nhi = whi * v;
    float nbN = __shfl_up_sync(0xffffffffu, Nhi, 1);
    float nbD = __shfl_up_sync(0xffffffffu, whi, 1);
    int   nbL = __shfl_up_sync(0xffffffffu, hi_lin, 1);

    bool mrg = (lane > 0) && (nbL == lo_lin);
    unsigned bal = __ballot_sync(0xffffffffu, mrg);
    bool absorbed = (bal & (2u << lane)) != 0u;   // lane 31: (2u<<31)==0 -> false

    float addN = mrg ? nbN : 0.0f;
    float addD = mrg ? nbD : 0.0f;

    red_add_v2(&g_acc[2 * lo_lin], wlo * v + addN, wlo + addD);
    if (!absorbed)
        red_add_v2(&g_acc[2 * hi_lin], Nhi, whi);
}

// ---------------------------------------------------------------------------
// Splat: warp lanes span w; (b,h,s) warp-uniform (=> orientation warp-uniform).
// Block = 8 warps covering 8 consecutive slices for the same (b, h, w-chunk).
// vol read staged through a padded smem tile (coalesced load, conflict-free
// readback). Grid = B * 9 * H * 4 = 18432 blocks of 256.
// ---------------------------------------------------------------------------
__global__ __launch_bounds__(256) void splat_kernel(
    const float* __restrict__ vol,    // (B,H,W,S,1)
    const float* __restrict__ trf)    // (B,S,3,4)
{
    __shared__ float sv[32 * 9];      // [w_local * 9 + s_local]

    int tid  = threadIdx.x;
    int lane = tid & 31;
    int wid  = tid >> 5;
    int blk  = blockIdx.x;

    int wc = blk & 3;                 // w chunk (0..3)
    int h  = (blk >> 2) & 127;
    int sc = (blk >> 9) % 9;          // s chunk (0..8)
    int b  = blk / 4608;

    // Stage vol[b, h, wc*32 .. +31, sc*8 .. +7] into smem.
    {
        int wl = tid >> 3;            // 0..31
        int sl = tid & 7;             // 0..7
        const float* src = vol + (((size_t)(b * HH + h) * WW + wc * 32) * SS
                                  + sc * 8);
        sv[wl * 9 + sl] = src[wl * SS + sl];
    }
    __syncthreads();

    int s = sc * 8 + wid;             // warp-uniform
    int w = wc * 32 + lane;

    float v = sv[lane * 9 + wid];     // conflict-free (stride 9)

    const float* Ap = trf + (size_t)(b * SS + s) * 12;
    float A00 = Ap[0] + 1.0f, A01 = Ap[1],        A02 = Ap[2],         A03 = Ap[3];
    float A10 = Ap[4],        A11 = Ap[5] + 1.0f, A12 = Ap[6],         A13 = Ap[7];
    float A20 = Ap[8],        A21 = Ap[9],        A22 = Ap[10] + 1.0f, A23 = Ap[11];

    int o = s / SPS;                  // 0=axi, 1=cor, 2=sag  (warp-uniform)
    float t = (float)(s % SPS) * ST_RATIO;

    float bx, by, bz;
    if (o == 0)      { bx = (float)h; by = (float)w; bz = t; }
    else if (o == 1) { bx = (float)h; by = t;        bz = (float)w; }
    else             { bx = t;        by = (float)h; bz = (float)w; }

    float x = A00 * bx + A01 * by + A02 * bz + A03;
    float y = A10 * bx + A11 * by + A12 * bz + A13;
    float z = A20 * bx + A21 * by + A22 * bz + A23 + 1.0f;

    float x0f = floorf(x), y0f = floorf(y), z0f = floorf(z);
    float wx = x - x0f, wy = y - y0f, wz = z - z0f;
    int x0 = (int)x0f, y0 = (int)y0f, z0 = (int)z0f;

    // clipped indices + validity masks (as weights)
    int cx0 = min(max(x0,     0), HH - 1);
    int cx1 = min(max(x0 + 1, 0), HH - 1);
    int cy0 = min(max(y0,     0), WW - 1);
    int cy1 = min(max(y0 + 1, 0), WW - 1);
    int cz0 = min(max(z0,     0), ZV - 1);
    int cz1 = min(max(z0 + 1, 0), ZV - 1);
    float vx0 = (x0 >= 0 && x0 < HH)         ? 1.0f : 0.0f;
    float vx1 = (x0 + 1 >= 0 && x0 + 1 < HH) ? 1.0f : 0.0f;
    float vy0 = (y0 >= 0 && y0 < WW)         ? 1.0f : 0.0f;
    float vy1 = (y0 + 1 >= 0 && y0 + 1 < WW) ? 1.0f : 0.0f;
    float vz0 = (z0 >= 0 && z0 < ZV)         ? 1.0f : 0.0f;
    float vz1 = (z0 + 1 >= 0 && z0 + 1 < ZV) ? 1.0f : 0.0f;

    float fx0 = (1.0f - wx) * vx0, fx1 = wx * vx1;
    float fy0 = (1.0f - wy) * vy0, fy1 = wy * vy1;
    float fz0 = (1.0f - wz) * vz0, fz1 = wz * vz1;

    int base_b = b * HH;

    if (o == 0) {
        // axi: y varies with lane -> merge along y (address delta = ZV)
        #pragma unroll
        for (int dx = 0; dx < 2; dx++) {
            int   cx  = dx ? cx1 : cx0;
            float fxm = dx ? fx1 : fx0;
            int row = (base_b + cx) * WW;
            #pragma unroll
            for (int dz = 0; dz < 2; dz++) {
                int   cz  = dz ? cz1 : cz0;
                float fxz = fxm * (dz ? fz1 : fz0);
                int lo_lin = (row + cy0) * ZV + cz;
                int hi_lin = (row + cy1) * ZV + cz;
                emit_pair(lane, lo_lin, hi_lin, fxz * fy0, fxz * fy1, v);
            }
        }
    } else {
        // cor/sag: z varies with lane -> merge along z (address delta = 1)
        #pragma unroll
        for (int dx = 0; dx < 2; dx++) {
            int   cx  = dx ? cx1 : cx0;
            float fxm = dx ? fx1 : fx0;
            int row = (base_b + cx) * WW;
            #pragma unroll
            for (int dy = 0; dy < 2; dy++) {
                int   cy  = dy ? cy1 : cy0;
                float fxy = fxm * (dy ? fy1 : fy0);
                int lin_xy = (row + cy) * ZV;
                emit_pair(lane, lin_xy + cz0, lin_xy + cz1, fxy * fz0, fxy * fz1, v);
            }
        }
    }
}

// ---------------------------------------------------------------------------
// Finalize: crop z[1:1+ZS], split interleaved N/D, where(D<=0, 1, D).
// Coalesced mapping (consecutive threads -> consecutive z) with ILP=2:
// each thread handles z and z+60 of the same (b,h,w) column.
// ---------------------------------------------------------------------------
__global__ __launch_bounds__(256) void finalize_kernel(float* __restrict__ out)
{
    int j = blockIdx.x * blockDim.x + threadIdx.x;   // OUT_PER/2 threads
    int z   = j % 60;
    int hwb = j / 60;

    const float2* acc = reinterpret_cast<const float2*>(g_acc);
    int lin = hwb * ZV + z + 1;
    float2 pa = acc[lin];
    float2 pb = acc[lin + 60];

    int oj = hwb * ZS + z;
    out[oj]                 = pa.x;
    out[oj + 60]            = pb.x;
    out[OUT_PER + oj]       = (pa.y > 0.0f) ? pa.y : 1.0f;
    out[OUT_PER + oj + 60]  = (pb.y > 0.0f) ? pb.y : 1.0f;
}

// ---------------------------------------------------------------------------
extern "C" void kernel_launch(void* const* d_in, const int* in_sizes, int n_in,
                              void* d_out, int out_size)
{
    const float* vol = (const float*)d_in[0];
    const float* trf = (const float*)d_in[1];
    float* out = (float*)d_out;

    splat_kernel<<<BB * 9 * HH * 4, 256>>>(vol, trf);
    finalize_kernel<<<(OUT_PER / 2) / 256, 256>>>(out);

    // Restore the all-zero invariant for the next replay; also leaves the
    // accumulator zeroed and warm in L2 for the next splat.
    void* acc_ptr = nullptr;
    cudaGetSymbolAddress(&acc_ptr, g_acc);
    cudaMemsetAsync(acc_ptr, 0, sizeof(float) * 2 * VOXELS, 0);
}

// round 8
// speedup vs baseline: 2.0051x; 1.2003x over previous
#include <cuda_runtime.h>
#include <cstdint>

// ---- problem constants (match reference) ----
#define BB 4
#define HH 128
#define WW 128
#define SS 72
#define SPS 24          // slices per stack
#define ZS 120          // z_scale
#define ZV 122          // padded depth
#define ST_RATIO 5.0f

#define VOXELS (BB * HH * WW * ZV)      // 7,995,392
#define PIXELS (BB * HH * WW * SS)      // 4,718,592
#define OUT_PER (BB * HH * WW * ZS)     // 7,864,320
#define HWSZ   (HH * WW)                // 16384

// Interleaved scratch: [2*lin]=N, [2*lin+1]=D. 64 MB, L2-resident.
// Tail cudaMemsetAsync restores the all-zero invariant after every execution.
__device__ __align__(16) float g_acc[2 * VOXELS];

__device__ __forceinline__ void red_add_v2(float* p, float a, float b) {
    asm volatile("red.global.add.v2.f32 [%0], {%1, %2};"
                 :: "l"(p), "f"(a), "f"(b) : "memory");
}

// Per-axis corner terms: clipped address contributions + masked weights.
struct Axis { int t0, t1; float f0, f1; };

__device__ __forceinline__ Axis axis_eval(float q, int E, int St) {
    float qf = floorf(q);
    int q0 = (int)qf;
    float fr = q - qf;
    int i0 = min(max(q0, 0), E - 1);
    int i1 = min(max(q0 + 1, 0), E - 1);
    Axis a;
    a.t0 = i0 * St;
    a.t1 = i1 * St;
    a.f0 = (q0 >= 0 && q0 < E)     ? (1.0f - fr) : 0.0f;
    a.f1 = (q0 >= -1 && q0 < E - 1) ? fr          : 0.0f;
    return a;
}

// ---------------------------------------------------------------------------
// Splat. Warp = 32 lanes spanning full w (v-merge runs of 32). Each thread
// serially processes a chain of 4 h-pixels (u-axis), carrying the u1-row of
// pixel p in registers and merging it into pixel p+1's u0-row on exact
// address equality (sum-preserving; no extra warp communication).
// Axis roles per orientation:
//   axi: u=x(h, stride W*ZV)  v=y(w, stride ZV)  c=z(stride 1)
//   cor: u=x(h, stride W*ZV)  v=z(w, stride 1)   c=y(stride ZV)
//   sag: u=y(h, stride ZV)    v=z(w, stride 1)   c=x(stride W*ZV)
// Block = 8 warps = 8 slices for the same (b, 4-h chunk, 32-w chunk).
// Grid = B * 9(sc) * 32(hc) * 4(wc) = 4608 blocks of 256.
// ---------------------------------------------------------------------------
__global__ __launch_bounds__(256) void splat_kernel(
    const float* __restrict__ vol,    // (B,H,W,S,1)
    const float* __restrict__ trf)    // (B,S,3,4)
{
    __shared__ float sv[4 * 32 * 9];  // [ (h_local*32 + w_local)*9 + s_local ]

    int tid  = threadIdx.x;
    int lane = tid & 31;
    int wid  = tid >> 5;
    int blk  = blockIdx.x;

    int wc = blk & 3;
    int tt = blk >> 2;
    int hc = tt & 31;  tt >>= 5;
    int sc = tt % 9;
    int b  = tt / 9;

    int h0 = hc * 4, w0 = wc * 32;
    int s  = sc * 8 + wid;            // warp-uniform

    // Stage vol[b, h0..h0+3, w0..w0+31, sc*8..sc*8+7] into smem (coalesced:
    // each warp reads 4 (h,w)-rows x 8 contiguous s floats = 4 full sectors).
    {
        const float* base = vol + (((size_t)(b * HH + h0) * WW + w0) * SS + sc * 8);
        #pragma unroll
        for (int it = 0; it < 4; it++) {
            int idx = it * 256 + tid;         // 0..1023
            int hh = idx >> 8;
            int wl = (idx >> 3) & 31;
            int sl = idx & 7;
            sv[(hh * 32 + wl) * 9 + sl] = base[((size_t)hh * WW + wl) * SS + sl];
        }
    }
    __syncthreads();

    const float* Ap = trf + (size_t)(b * SS + s) * 12;
    float A00 = Ap[0] + 1.0f, A01 = Ap[1],        A02 = Ap[2],         A03 = Ap[3];
    float A10 = Ap[4],        A11 = Ap[5] + 1.0f, A12 = Ap[6],         A13 = Ap[7];
    float A20 = Ap[8],        A21 = Ap[9],        A22 = Ap[10] + 1.0f, A23 = Ap[11];

    int o = s / SPS;                  // warp-uniform orientation
    float tc = (float)(s % SPS) * ST_RATIO;
    int w = w0 + lane;
    int bb = b * HH * WW * ZV;

    // carry per c-corner: pixel p's u1-row awaiting merge with p+1's u0-row
    int   cLoA[2] = { -1, -1 };
    float cLoN[2], cLoD[2];
    int   cHiA[2];
    float cHiN[2], cHiD[2];
    bool  cHiS[2] = { false, false };

    #pragma unroll
    for (int p = 0; p < 4; p++) {
        int h = h0 + p;
        float v = sv[(p * 32 + lane) * 9 + wid];   // conflict-free (stride 9)

        float bx, by, bz;
        if (o == 0)      { bx = (float)h; by = (float)w; bz = tc; }
        else if (o == 1) { bx = (float)h; by = tc;       bz = (float)w; }
        else             { bx = tc;       by = (float)h; bz = (float)w; }

        float x = A00 * bx + A01 * by + A02 * bz + A03;
        float y = A10 * bx + A11 * by + A12 * bz + A13;
        float z = A20 * bx + A21 * by + A22 * bz + A23 + 1.0f;

        Axis U, V, C;
        if (o == 0) {
            U = axis_eval(x, HH, WW * ZV);
            V = axis_eval(y, WW, ZV);
            C = axis_eval(z, ZV, 1);
        } else if (o == 1) {
            U = axis_eval(x, HH, WW * ZV);
            V = axis_eval(z, ZV, 1);
            C = axis_eval(y, WW, ZV);
        } else {
            U = axis_eval(y, WW, ZV);
            V = axis_eval(z, ZV, 1);
            C = axis_eval(x, HH, WW * ZV);
        }

        #pragma unroll
        for (int c = 0; c < 2; c++) {
            int   ct = c ? C.t1 : C.t0;
            float fc = c ? C.f1 : C.f0;

            int   rL[2], rH[2];
            float rAccN[2], rAccD[2], rHiN[2], rHiD[2];
            bool  rS[2];

            // v-merge along the 32-lane w run, for both u rows
            #pragma unroll
            for (int r = 0; r < 2; r++) {
                int   ut = r ? U.t1 : U.t0;
                float fu = r ? U.f1 : U.f0;
                int L  = bb + ut + V.t0 + ct;
                int Hh = bb + ut + V.t1 + ct;
                float wlo = fu * V.f0 * fc;
                float whi = fu * V.f1 * fc;
                float NhiV = whi * v;

                float nbN = __shfl_up_sync(0xffffffffu, NhiV, 1);
                float nbD = __shfl_up_sync(0xffffffffu, whi, 1);
                int   nbH = __shfl_up_sync(0xffffffffu, Hh, 1);
                bool mrg = (lane > 0) && (nbH == L);
                unsigned bal = __ballot_sync(0xffffffffu, mrg);
                bool absorbed = (bal & (2u << lane)) != 0u;  // lane31 -> false

                rL[r]   = L;
                rAccN[r] = wlo * v + (mrg ? nbN : 0.0f);
                rAccD[r] = wlo     + (mrg ? nbD : 0.0f);
                rH[r]   = Hh;
                rHiN[r] = NhiV;
                rHiD[r] = whi;
                rS[r]   = !absorbed;
            }

            // u-chain: absorb previous pixel's u1-row (carry) into this u0-row
            if (cLoA[c] >= 0) {
                if (cLoA[c] == rL[0]) {
                    rAccN[0] += cLoN[c];
                    rAccD[0] += cLoD[c];
                } else {
                    red_add_v2(&g_acc[2 * cLoA[c]], cLoN[c], cLoD[c]);
                }
                if (cHiS[c]) {
                    if (rS[0] && cHiA[c] == rH[0]) {
                        rHiN[0] += cHiN[c];
                        rHiD[0] += cHiD[c];
                    } else {
                        red_add_v2(&g_acc[2 * cHiA[c]], cHiN[c], cHiD[c]);
                    }
                }
            }

            // emit u0-row
            red_add_v2(&g_acc[2 * rL[0]], rAccN[0], rAccD[0]);
            if (rS[0])
                red_add_v2(&g_acc[2 * rH[0]], rHiN[0], rHiD[0]);

            // u1-row becomes the new carry
            cLoA[c] = rL[1]; cLoN[c] = rAccN[1]; cLoD[c] = rAccD[1];
            cHiA[c] = rH[1]; cHiN[c] = rHiN[1]; cHiD[c] = rHiD[1];
            cHiS[c] = rS[1];
        }
    }

    // flush remaining carries
    #pragma unroll
    for (int c = 0; c < 2; c++) {
        if (cLoA[c] >= 0) {
            red_add_v2(&g_acc[2 * cLoA[c]], cLoN[c], cLoD[c]);
            if (cHiS[c])
                red_add_v2(&g_acc[2 * cHiA[c]], cHiN[c], cHiD[c]);
        }
    }
}

// ---------------------------------------------------------------------------
// Finalize: crop z[1:1+ZS], split interleaved N/D, where(D<=0, 1, D).
// Coalesced mapping (consecutive threads -> consecutive z) with ILP=4:
// each thread handles z, z+30, z+60, z+90 of the same (b,h,w) column.
// ---------------------------------------------------------------------------
__global__ __launch_bounds__(256) void finalize_kernel(float* __restrict__ out)
{
    int j = blockIdx.x * blockDim.x + threadIdx.x;   // OUT_PER/4 threads
    int z   = j % 30;
    int hwb = j / 30;

    const float2* acc = reinterpret_cast<const float2*>(g_acc);
    int lin = hwb * ZV + z + 1;
    float2 p0 = acc[lin];
    float2 p1 = acc[lin + 30];
    float2 p2 = acc[lin + 60];
    float2 p3 = acc[lin + 90];

    int oj = hwb * ZS + z;
    out[oj]      = p0.x;
    out[oj + 30] = p1.x;
    out[oj + 60] = p2.x;
    out[oj + 90] = p3.x;
    out[OUT_PER + oj]      = (p0.y > 0.0f) ? p0.y : 1.0f;
    out[OUT_PER + oj + 30] = (p1.y > 0.0f) ? p1.y : 1.0f;
    out[OUT_PER + oj + 60] = (p2.y > 0.0f) ? p2.y : 1.0f;
    out[OUT_PER + oj + 90] = (p3.y > 0.0f) ? p3.y : 1.0f;
}

// ---------------------------------------------------------------------------
extern "C" void kernel_launch(void* const* d_in, const int* in_sizes, int n_in,
                              void* d_out, int out_size)
{
    const float* vol = (const float*)d_in[0];
    const float* trf = (const float*)d_in[1];
    float* out = (float*)d_out;

    splat_kernel<<<BB * 9 * 32 * 4, 256>>>(vol, trf);
    finalize_kernel<<<(OUT_PER / 4) / 256, 256>>>(out);

    // Restore the all-zero invariant for the next replay; also leaves the
    // accumulator zeroed and warm in L2 for the next splat.
    void* acc_ptr = nullptr;
    cudaGetSymbolAddress(&acc_ptr, g_acc);
    cudaMemsetAsync(acc_ptr, 0, sizeof(float) * 2 * VOXELS, 0);
}

// round 9
// speedup vs baseline: 2.1623x; 1.0784x over previous
#include <cuda_runtime.h>
#include <cstdint>

// ---- problem constants (match reference) ----
#define BB 4
#define HH 128
#define WW 128
#define SS 72
#define SPS 24          // slices per stack
#define ZS 120          // z_scale
#define ZV 122          // padded depth
#define ST_RATIO 5.0f

#define VOXELS (BB * HH * WW * ZV)      // 7,995,392
#define PIXELS (BB * HH * WW * SS)      // 4,718,592
#define OUT_PER (BB * HH * WW * ZS)     // 7,864,320
#define HWSZ   (HH * WW)                // 16384

#define CHAIN 8                          // h-pixels per thread (u-chain length)

// Interleaved scratch: [2*lin]=N, [2*lin+1]=D. 64 MB, L2-resident.
// Tail cudaMemsetAsync restores the all-zero invariant after every execution.
__device__ __align__(16) float g_acc[2 * VOXELS];

__device__ __forceinline__ void red_add_v2(float* p, float a, float b) {
    asm volatile("red.global.add.v2.f32 [%0], {%1, %2};"
                 :: "l"(p), "f"(a), "f"(b) : "memory");
}

// Per-axis corner terms: clipped address contributions + masked weights.
struct Axis { int t0, t1; float f0, f1; };

__device__ __forceinline__ Axis axis_eval(float q, int E, int St) {
    float qf = floorf(q);
    int q0 = (int)qf;
    float fr = q - qf;
    int i0 = min(max(q0, 0), E - 1);
    int i1 = min(max(q0 + 1, 0), E - 1);
    Axis a;
    a.t0 = i0 * St;
    a.t1 = i1 * St;
    a.f0 = (q0 >= 0 && q0 < E)      ? (1.0f - fr) : 0.0f;
    a.f1 = (q0 >= -1 && q0 < E - 1) ? fr          : 0.0f;
    return a;
}

// ---------------------------------------------------------------------------
// Splat. Warp = 32 lanes spanning full w (v-merge runs of 32). Each thread
// serially processes a chain of CHAIN h-pixels (u-axis), carrying the u1-row
// of pixel p in registers and merging it into pixel p+1's u0-row on exact
// address equality (sum-preserving; no extra warp communication).
// Axis roles per orientation:
//   axi: u=x(h, stride W*ZV)  v=y(w, stride ZV)  c=z(stride 1)
//   cor: u=x(h, stride W*ZV)  v=z(w, stride 1)   c=y(stride ZV)
//   sag: u=y(h, stride ZV)    v=z(w, stride 1)   c=x(stride W*ZV)
// Block = 8 warps = 8 slices for the same (b, CHAIN-h chunk, 32-w chunk).
// Grid = B * 9(sc) * (128/CHAIN)(hc) * 4(wc) = 2304 blocks of 256.
// ---------------------------------------------------------------------------
__global__ __launch_bounds__(256) void splat_kernel(
    const float* __restrict__ vol,    // (B,H,W,S,1)
    const float* __restrict__ trf)    // (B,S,3,4)
{
    __shared__ float sv[CHAIN * 32 * 9];  // [ (h_local*32 + w_local)*9 + s_local ]

    int tid  = threadIdx.x;
    int lane = tid & 31;
    int wid  = tid >> 5;
    int blk  = blockIdx.x;

    int wc = blk & 3;
    int tt = blk >> 2;
    int hc = tt & 15;  tt >>= 4;
    int sc = tt % 9;
    int b  = tt / 9;

    int h0 = hc * CHAIN, w0 = wc * 32;
    int s  = sc * 8 + wid;            // warp-uniform

    // Stage vol[b, h0..h0+CHAIN-1, w0..w0+31, sc*8..+7] into smem.
    // Each staging warp reads 4 (h,w)-rows x 8 contiguous s floats = 4 full
    // 32B sectors -> sector-efficient.
    {
        const float* base = vol + (((size_t)(b * HH + h0) * WW + w0) * SS + sc * 8);
        #pragma unroll
        for (int it = 0; it < CHAIN; it++) {
            int idx = it * 256 + tid;         // 0 .. CHAIN*256-1
            int hh = idx >> 8;
            int wl = (idx >> 3) & 31;
            int sl = idx & 7;
            sv[(hh * 32 + wl) * 9 + sl] = base[((size_t)hh * WW + wl) * SS + sl];
        }
    }
    __syncthreads();

    const float* Ap = trf + (size_t)(b * SS + s) * 12;
    float A00 = Ap[0] + 1.0f, A01 = Ap[1],        A02 = Ap[2],         A03 = Ap[3];
    float A10 = Ap[4],        A11 = Ap[5] + 1.0f, A12 = Ap[6],         A13 = Ap[7];
    float A20 = Ap[8],        A21 = Ap[9],        A22 = Ap[10] + 1.0f, A23 = Ap[11];

    int o = s / SPS;                  // warp-uniform orientation
    float tc = (float)(s % SPS) * ST_RATIO;
    int w = w0 + lane;
    int bb = b * HH * WW * ZV;

    // carry per c-corner: pixel p's u1-row awaiting merge with p+1's u0-row
    int   cLoA[2] = { -1, -1 };
    float cLoN[2], cLoD[2];
    int   cHiA[2];
    float cHiN[2], cHiD[2];
    bool  cHiS[2] = { false, false };

    for (int p = 0; p < CHAIN; p++) {
        int h = h0 + p;
        float v = sv[(p * 32 + lane) * 9 + wid];   // conflict-free (stride 9)

        float bx, by, bz;
        if (o == 0)      { bx = (float)h; by = (float)w; bz = tc; }
        else if (o == 1) { bx = (float)h; by = tc;       bz = (float)w; }
        else             { bx = tc;       by = (float)h; bz = (float)w; }

        float x = A00 * bx + A01 * by + A02 * bz + A03;
        float y = A10 * bx + A11 * by + A12 * bz + A13;
        float z = A20 * bx + A21 * by + A22 * bz + A23 + 1.0f;

        Axis U, V, C;
        if (o == 0) {
            U = axis_eval(x, HH, WW * ZV);
            V = axis_eval(y, WW, ZV);
            C = axis_eval(z, ZV, 1);
        } else if (o == 1) {
            U = axis_eval(x, HH, WW * ZV);
            V = axis_eval(z, ZV, 1);
            C = axis_eval(y, WW, ZV);
        } else {
            U = axis_eval(y, WW, ZV);
            V = axis_eval(z, ZV, 1);
            C = axis_eval(x, HH, WW * ZV);
        }

        #pragma unroll
        for (int c = 0; c < 2; c++) {
            int   ct = c ? C.t1 : C.t0;
            float fc = c ? C.f1 : C.f0;

            int   rL[2], rH[2];
            float rAccN[2], rAccD[2], rHiN[2], rHiD[2];
            bool  rS[2];

            // v-merge along the 32-lane w run, for both u rows
            #pragma unroll
            for (int r = 0; r < 2; r++) {
                int   ut = r ? U.t1 : U.t0;
                float fu = r ? U.f1 : U.f0;
                int L  = bb + ut + V.t0 + ct;
                int Hh = bb + ut + V.t1 + ct;
                float wlo = fu * V.f0 * fc;
                float whi = fu * V.f1 * fc;
                float NhiV = whi * v;

                float nbN = __shfl_up_sync(0xffffffffu, NhiV, 1);
                float nbD = __shfl_up_sync(0xffffffffu, whi, 1);
                int   nbH = __shfl_up_sync(0xffffffffu, Hh, 1);
                bool mrg = (lane > 0) && (nbH == L);
                unsigned bal = __ballot_sync(0xffffffffu, mrg);
                bool absorbed = (bal & (2u << lane)) != 0u;  // lane31 -> false

                rL[r]    = L;
                rAccN[r] = wlo * v + (mrg ? nbN : 0.0f);
                rAccD[r] = wlo     + (mrg ? nbD : 0.0f);
                rH[r]    = Hh;
                rHiN[r]  = NhiV;
                rHiD[r]  = whi;
                rS[r]    = !absorbed;
            }

            // u-chain: absorb previous pixel's u1-row (carry) into this u0-row
            if (cLoA[c] >= 0) {
                if (cLoA[c] == rL[0]) {
                    rAccN[0] += cLoN[c];
                    rAccD[0] += cLoD[c];
                } else {
                    red_add_v2(&g_acc[2 * cLoA[c]], cLoN[c], cLoD[c]);
                }
                if (cHiS[c]) {
                    if (rS[0] && cHiA[c] == rH[0]) {
                        rHiN[0] += cHiN[c];
                        rHiD[0] += cHiD[c];
                    } else {
                        red_add_v2(&g_acc[2 * cHiA[c]], cHiN[c], cHiD[c]);
                    }
                }
            }

            // emit u0-row
            red_add_v2(&g_acc[2 * rL[0]], rAccN[0], rAccD[0]);
            if (rS[0])
                red_add_v2(&g_acc[2 * rH[0]], rHiN[0], rHiD[0]);

            // u1-row becomes the new carry
            cLoA[c] = rL[1]; cLoN[c] = rAccN[1]; cLoD[c] = rAccD[1];
            cHiA[c] = rH[1]; cHiN[c] = rHiN[1]; cHiD[c] = rHiD[1];
            cHiS[c] = rS[1];
        }
    }

    // flush remaining carries
    #pragma unroll
    for (int c = 0; c < 2; c++) {
        if (cLoA[c] >= 0) {
            red_add_v2(&g_acc[2 * cLoA[c]], cLoN[c], cLoD[c]);
            if (cHiS[c])
                red_add_v2(&g_acc[2 * cHiA[c]], cHiN[c], cHiD[c]);
        }
    }
}

// ---------------------------------------------------------------------------
// Finalize: crop z[1:1+ZS], split interleaved N/D, where(D<=0, 1, D).
// Coalesced mapping (consecutive threads -> consecutive z) with ILP=4:
// each thread handles z, z+30, z+60, z+90 of the same (b,h,w) column.
// ---------------------------------------------------------------------------
__global__ __launch_bounds__(256) void finalize_kernel(float* __restrict__ out)
{
    int j = blockIdx.x * blockDim.x + threadIdx.x;   // OUT_PER/4 threads
    int z   = j % 30;
    int hwb = j / 30;

    const float2* acc = reinterpret_cast<const float2*>(g_acc);
    int lin = hwb * ZV + z + 1;
    float2 p0 = acc[lin];
    float2 p1 = acc[lin + 30];
    float2 p2 = acc[lin + 60];
    float2 p3 = acc[lin + 90];

    int oj = hwb * ZS + z;
    out[oj]      = p0.x;
    out[oj + 30] = p1.x;
    out[oj + 60] = p2.x;
    out[oj + 90] = p3.x;
    out[OUT_PER + oj]      = (p0.y > 0.0f) ? p0.y : 1.0f;
    out[OUT_PER + oj + 30] = (p1.y > 0.0f) ? p1.y : 1.0f;
    out[OUT_PER + oj + 60] = (p2.y > 0.0f) ? p2.y : 1.0f;
    out[OUT_PER + oj + 90] = (p3.y > 0.0f) ? p3.y : 1.0f;
}

// ---------------------------------------------------------------------------
extern "C" void kernel_launch(void* const* d_in, const int* in_sizes, int n_in,
                              void* d_out, int out_size)
{
    const float* vol = (const float*)d_in[0];
    const float* trf = (const float*)d_in[1];
    float* out = (float*)d_out;

    splat_kernel<<<BB * 9 * (HH / CHAIN) * 4, 256>>>(vol, trf);
    finalize_kernel<<<(OUT_PER / 4) / 256, 256>>>(out);

    // Restore the all-zero invariant for the next replay; also leaves the
    // accumulator zeroed and warm in L2 for the next splat.
    void* acc_ptr = nullptr;
    cudaGetSymbolAddress(&acc_ptr, g_acc);
    cudaMemsetAsync(acc_ptr, 0, sizeof(float) * 2 * VOXELS, 0);
}

// round 10
// speedup vs baseline: 2.1641x; 1.0008x over previous
#include <cuda_runtime.h>
#include <cstdint>

// ---- problem constants (match reference) ----
#define BB 4
#define HH 128
#define WW 128
#define SS 72
#define SPS 24          // slices per stack
#define ZS 120          // z_scale
#define ZV 122          // padded depth
#define ST_RATIO 5.0f

#define VOXELS (BB * HH * WW * ZV)      // 7,995,392
#define PIXELS (BB * HH * WW * SS)      // 4,718,592
#define OUT_PER (BB * HH * WW * ZS)     // 7,864,320
#define HWSZ   (HH * WW)                // 16384

#define CHAIN 16                         // h-pixels per thread (u-chain length)

// Interleaved scratch: [2*lin]=N, [2*lin+1]=D. 64 MB, L2-resident.
// Tail cudaMemsetAsync restores the all-zero invariant after every execution.
__device__ __align__(16) float g_acc[2 * VOXELS];

__device__ __forceinline__ void red_add_v2(float* p, float a, float b) {
    asm volatile("red.global.add.v2.f32 [%0], {%1, %2};"
                 :: "l"(p), "f"(a), "f"(b) : "memory");
}

// Per-axis corner terms: clipped address contributions + masked weights.
struct Axis { int t0, t1; float f0, f1; };

__device__ __forceinline__ Axis axis_eval(float q, int E, int St) {
    float qf = floorf(q);
    int q0 = (int)qf;
    float fr = q - qf;
    int i0 = min(max(q0, 0), E - 1);
    int i1 = min(max(q0 + 1, 0), E - 1);
    Axis a;
    a.t0 = i0 * St;
    a.t1 = i1 * St;
    a.f0 = (q0 >= 0 && q0 < E)      ? (1.0f - fr) : 0.0f;
    a.f1 = (q0 >= -1 && q0 < E - 1) ? fr          : 0.0f;
    return a;
}

// ---------------------------------------------------------------------------
// Splat. Warp = 32 lanes spanning full w (v-merge runs of 32). Each thread
// serially processes a chain of CHAIN h-pixels (u-axis), carrying the u1-row
// of pixel p in registers and merging it into pixel p+1's u0-row on exact
// address equality (sum-preserving; no extra warp communication).
// Axis roles per orientation:
//   axi: u=x(h, stride W*ZV)  v=y(w, stride ZV)  c=z(stride 1)
//   cor: u=x(h, stride W*ZV)  v=z(w, stride 1)   c=y(stride ZV)
//   sag: u=y(h, stride ZV)    v=z(w, stride 1)   c=x(stride W*ZV)
// Block = 8 warps = 8 slices for the same (b, CHAIN-h chunk, 32-w chunk).
// Grid = B * 9(sc) * (128/CHAIN)(hc) * 4(wc) = 1152 blocks of 256.
// ---------------------------------------------------------------------------
__global__ __launch_bounds__(256) void splat_kernel(
    const float* __restrict__ vol,    // (B,H,W,S,1)
    const float* __restrict__ trf)    // (B,S,3,4)
{
    __shared__ float sv[CHAIN * 32 * 9];  // [ (h_local*32 + w_local)*9 + s_local ]

    int tid  = threadIdx.x;
    int lane = tid & 31;
    int wid  = tid >> 5;
    int blk  = blockIdx.x;

    int wc = blk & 3;
    int tt = blk >> 2;
    int hc = tt & 7;   tt >>= 3;       // 128/CHAIN = 8 h-chunks
    int sc = tt % 9;
    int b  = tt / 9;

    int h0 = hc * CHAIN, w0 = wc * 32;
    int s  = sc * 8 + wid;            // warp-uniform

    // Stage vol[b, h0..h0+CHAIN-1, w0..w0+31, sc*8..+7] into smem.
    // Each staging warp reads 4 (h,w)-rows x 8 contiguous s floats = 4 full
    // 32B sectors -> sector-efficient.
    {
        const float* base = vol + (((size_t)(b * HH + h0) * WW + w0) * SS + sc * 8);
        #pragma unroll
        for (int it = 0; it < CHAIN; it++) {
            int idx = it * 256 + tid;         // 0 .. CHAIN*256-1
            int hh = idx >> 8;
            int wl = (idx >> 3) & 31;
            int sl = idx & 7;
            sv[(hh * 32 + wl) * 9 + sl] = base[((size_t)hh * WW + wl) * SS + sl];
        }
    }
    __syncthreads();

    const float* Ap = trf + (size_t)(b * SS + s) * 12;
    float A00 = Ap[0] + 1.0f, A01 = Ap[1],        A02 = Ap[2],         A03 = Ap[3];
    float A10 = Ap[4],        A11 = Ap[5] + 1.0f, A12 = Ap[6],         A13 = Ap[7];
    float A20 = Ap[8],        A21 = Ap[9],        A22 = Ap[10] + 1.0f, A23 = Ap[11];

    int o = s / SPS;                  // warp-uniform orientation
    float tc = (float)(s % SPS) * ST_RATIO;
    int w = w0 + lane;
    int bb = b * HH * WW * ZV;

    // carry per c-corner: pixel p's u1-row awaiting merge with p+1's u0-row
    int   cLoA[2] = { -1, -1 };
    float cLoN[2], cLoD[2];
    int   cHiA[2];
    float cHiN[2], cHiD[2];
    bool  cHiS[2] = { false, false };

    for (int p = 0; p < CHAIN; p++) {
        int h = h0 + p;
        float v = sv[(p * 32 + lane) * 9 + wid];   // conflict-free (stride 9)

        float bx, by, bz;
        if (o == 0)      { bx = (float)h; by = (float)w; bz = tc; }
        else if (o == 1) { bx = (float)h; by = tc;       bz = (float)w; }
        else             { bx = tc;       by = (float)h; bz = (float)w; }

        float x = A00 * bx + A01 * by + A02 * bz + A03;
        float y = A10 * bx + A11 * by + A12 * bz + A13;
        float z = A20 * bx + A21 * by + A22 * bz + A23 + 1.0f;

        Axis U, V, C;
        if (o == 0) {
            U = axis_eval(x, HH, WW * ZV);
            V = axis_eval(y, WW, ZV);
            C = axis_eval(z, ZV, 1);
        } else if (o == 1) {
            U = axis_eval(x, HH, WW * ZV);
            V = axis_eval(z, ZV, 1);
            C = axis_eval(y, WW, ZV);
        } else {
            U = axis_eval(y, WW, ZV);
            V = axis_eval(z, ZV, 1);
            C = axis_eval(x, HH, WW * ZV);
        }

        #pragma unroll
        for (int c = 0; c < 2; c++) {
            int   ct = c ? C.t1 : C.t0;
            float fc = c ? C.f1 : C.f0;

            int   rL[2], rH[2];
            float rAccN[2], rAccD[2], rHiN[2], rHiD[2];
            bool  rS[2];

            // v-merge along the 32-lane w run, for both u rows
            #pragma unroll
            for (int r = 0; r < 2; r++) {
                int   ut = r ? U.t1 : U.t0;
                float fu = r ? U.f1 : U.f0;
                int L  = bb + ut + V.t0 + ct;
                int Hh = bb + ut + V.t1 + ct;
                float wlo = fu * V.f0 * fc;
                float whi = fu * V.f1 * fc;
                float NhiV = whi * v;

                float nbN = __shfl_up_sync(0xffffffffu, NhiV, 1);
                float nbD = __shfl_up_sync(0xffffffffu, whi, 1);
                int   nbH = __shfl_up_sync(0xffffffffu, Hh, 1);
                bool mrg = (lane > 0) && (nbH == L);
                unsigned bal = __ballot_sync(0xffffffffu, mrg);
                bool absorbed = (bal & (2u << lane)) != 0u;  // lane31 -> false

                rL[r]    = L;
                rAccN[r] = wlo * v + (mrg ? nbN : 0.0f);
                rAccD[r] = wlo     + (mrg ? nbD : 0.0f);
                rH[r]    = Hh;
                rHiN[r]  = NhiV;
                rHiD[r]  = whi;
                rS[r]    = !absorbed;
            }

            // u-chain: absorb previous pixel's u1-row (carry) into this u0-row
            if (cLoA[c] >= 0) {
                if (cLoA[c] == rL[0]) {
                    rAccN[0] += cLoN[c];
                    rAccD[0] += cLoD[c];
                } else {
                    red_add_v2(&g_acc[2 * cLoA[c]], cLoN[c], cLoD[c]);
                }
                if (cHiS[c]) {
                    if (rS[0] && cHiA[c] == rH[0]) {
                        rHiN[0] += cHiN[c];
                        rHiD[0] += cHiD[c];
                    } else {
                        red_add_v2(&g_acc[2 * cHiA[c]], cHiN[c], cHiD[c]);
                    }
                }
            }

            // emit u0-row
            red_add_v2(&g_acc[2 * rL[0]], rAccN[0], rAccD[0]);
            if (rS[0])
                red_add_v2(&g_acc[2 * rH[0]], rHiN[0], rHiD[0]);

            // u1-row becomes the new carry
            cLoA[c] = rL[1]; cLoN[c] = rAccN[1]; cLoD[c] = rAccD[1];
            cHiA[c] = rH[1]; cHiN[c] = rHiN[1]; cHiD[c] = rHiD[1];
            cHiS[c] = rS[1];
        }
    }

    // flush remaining carries
    #pragma unroll
    for (int c = 0; c < 2; c++) {
        if (cLoA[c] >= 0) {
            red_add_v2(&g_acc[2 * cLoA[c]], cLoN[c], cLoD[c]);
            if (cHiS[c])
                red_add_v2(&g_acc[2 * cHiA[c]], cHiN[c], cHiD[c]);
        }
    }
}

// ---------------------------------------------------------------------------
// Finalize: crop z[1:1+ZS], split interleaved N/D, where(D<=0, 1, D).
// One warp per (b,h,w) column: 4 strided passes of 32 z values (last pass
// predicated to z<120). Every read wavefront is an aligned 256B run of
// consecutive pairs; stores are aligned 128B runs. ILP=4.
// Grid = HWSZ*BB/8 = 8192 blocks of 256 (8 warps = 8 columns per block).
// ---------------------------------------------------------------------------
__global__ __launch_bounds__(256) void finalize_kernel(float* __restrict__ out)
{
    int lane = threadIdx.x & 31;
    int col  = blockIdx.x * 8 + (threadIdx.x >> 5);   // global hwb column

    const float2* acc = reinterpret_cast<const float2*>(g_acc);
    int lin = col * ZV + 1;
    int oj  = col * ZS;

    float2 p0 = acc[lin + lane];
    float2 p1 = acc[lin + lane + 32];
    float2 p2 = acc[lin + lane + 64];
    float2 p3 = (lane < 24) ? acc[lin + lane + 96] : make_float2(0.f, 0.f);

    out[oj + lane]      = p0.x;
    out[oj + lane + 32] = p1.x;
    out[oj + lane + 64] = p2.x;
    out[OUT_PER + oj + lane]      = (p0.y > 0.0f) ? p0.y : 1.0f;
    out[OUT_PER + oj + lane + 32] = (p1.y > 0.0f) ? p1.y : 1.0f;
    out[OUT_PER + oj + lane + 64] = (p2.y > 0.0f) ? p2.y : 1.0f;
    if (lane < 24) {
        out[oj + lane + 96]           = p3.x;
        out[OUT_PER + oj + lane + 96] = (p3.y > 0.0f) ? p3.y : 1.0f;
    }
}

// ---------------------------------------------------------------------------
extern "C" void kernel_launch(void* const* d_in, const int* in_sizes, int n_in,
                              void* d_out, int out_size)
{
    const float* vol = (const float*)d_in[0];
    const float* trf = (const float*)d_in[1];
    float* out = (float*)d_out;

    splat_kernel<<<BB * 9 * (HH / CHAIN) * 4, 256>>>(vol, trf);
    finalize_kernel<<<(HWSZ * BB) / 8, 256>>>(out);

    // Restore the all-zero invariant for the next replay; also leaves the
    // accumulator zeroed and warm in L2 for the next splat.
    void* acc_ptr = nullptr;
    cudaGetSymbolAddress(&acc_ptr, g_acc);
    cudaMemsetAsync(acc_ptr, 0, sizeof(float) * 2 * VOXELS, 0);
}

// round 11
// speedup vs baseline: 2.2452x; 1.0375x over previous
#include <cuda_runtime.h>
#include <cstdint>

// ---- problem constants (match reference) ----
#define BB 4
#define HH 128
#define WW 128
#define SS 72
#define SPS 24          // slices per stack
#define ZS 120          // z_scale
#define ZV 122          // padded depth
#define ST_RATIO 5.0f

#define VOXELS (BB * HH * WW * ZV)      // 7,995,392
#define PIXELS (BB * HH * WW * SS)      // 4,718,592
#define OUT_PER (BB * HH * WW * ZS)     // 7,864,320
#define HWSZ   (HH * WW)                // 16384

#define CHAIN 16                         // h-pixels per thread (u-chain length)

// Interleaved scratch: [2*lin]=N, [2*lin+1]=D. 64 MB, L2-resident.
// Tail cudaMemsetAsync restores the all-zero invariant after every execution.
__device__ __align__(16) float g_acc[2 * VOXELS];

__device__ __forceinline__ void red_add_v2(float* p, float a, float b) {
    asm volatile("red.global.add.v2.f32 [%0], {%1, %2};"
                 :: "l"(p), "f"(a), "f"(b) : "memory");
}

__device__ __forceinline__ void red_add_v4(float* p, float a, float b,
                                           float c, float d) {
    asm volatile("red.global.add.v4.f32 [%0], {%1, %2, %3, %4};"
                 :: "l"(p), "f"(a), "f"(b), "f"(c), "f"(d) : "memory");
}

// Per-axis corner terms: clipped address contributions + masked weights.
struct Axis { int t0, t1; float f0, f1; };

__device__ __forceinline__ Axis axis_eval(float q, int E, int St) {
    float qf = floorf(q);
    int q0 = (int)qf;
    float fr = q - qf;
    int i0 = min(max(q0, 0), E - 1);
    int i1 = min(max(q0 + 1, 0), E - 1);
    Axis a;
    a.t0 = i0 * St;
    a.t1 = i1 * St;
    a.f0 = (q0 >= 0 && q0 < E)      ? (1.0f - fr) : 0.0f;
    a.f1 = (q0 >= -1 && q0 < E - 1) ? fr          : 0.0f;
    return a;
}

// ---------------------------------------------------------------------------
// Splat. Warp = 32 lanes spanning full w (v-merge runs of 32). Each thread
// serially processes a chain of CHAIN h-pixels (u-axis), carrying the u1-row
// of pixel p in registers and merging it into pixel p+1's u0-row on exact
// address equality (sum-preserving; no extra warp communication).
// Axis roles per orientation:
//   axi: u=x(h, stride W*ZV)  v=y(w, stride ZV)  c=z(stride 1)
//   cor: u=x(h, stride W*ZV)  v=z(w, stride 1)   c=y(stride ZV)
//   sag: u=y(h, stride ZV)    v=z(w, stride 1)   c=x(stride W*ZV)
// For axi (c stride 1), the per-pixel lo-row emissions for the two c-corners
// hit consecutive N/D pairs; when 16B-aligned and truly adjacent they fuse
// into a single red.global.add.v4.f32.
// Block = 8 warps = 8 slices for the same (b, CHAIN-h chunk, 32-w chunk).
// Grid = B * 9(sc) * (128/CHAIN)(hc) * 4(wc) = 1152 blocks of 256.
// ---------------------------------------------------------------------------
__global__ __launch_bounds__(256) void splat_kernel(
    const float* __restrict__ vol,    // (B,H,W,S,1)
    const float* __restrict__ trf)    // (B,S,3,4)
{
    __shared__ float sv[CHAIN * 32 * 9];  // [ (h_local*32 + w_local)*9 + s_local ]

    int tid  = threadIdx.x;
    int lane = tid & 31;
    int wid  = tid >> 5;
    int blk  = blockIdx.x;

    int wc = blk & 3;
    int tt = blk >> 2;
    int hc = tt & 7;   tt >>= 3;       // 128/CHAIN = 8 h-chunks
    int sc = tt % 9;
    int b  = tt / 9;

    int h0 = hc * CHAIN, w0 = wc * 32;
    int s  = sc * 8 + wid;            // warp-uniform

    // Stage vol[b, h0..h0+CHAIN-1, w0..w0+31, sc*8..+7] into smem (coalesced,
    // sector-efficient; pad-9 rows for conflict-free readback).
    {
        const float* base = vol + (((size_t)(b * HH + h0) * WW + w0) * SS + sc * 8);
        #pragma unroll
        for (int it = 0; it < CHAIN; it++) {
            int idx = it * 256 + tid;
            int hh = idx >> 8;
            int wl = (idx >> 3) & 31;
            int sl = idx & 7;
            sv[(hh * 32 + wl) * 9 + sl] = base[((size_t)hh * WW + wl) * SS + sl];
        }
    }
    __syncthreads();

    const float* Ap = trf + (size_t)(b * SS + s) * 12;
    float A00 = Ap[0] + 1.0f, A01 = Ap[1],        A02 = Ap[2],         A03 = Ap[3];
    float A10 = Ap[4],        A11 = Ap[5] + 1.0f, A12 = Ap[6],         A13 = Ap[7];
    float A20 = Ap[8],        A21 = Ap[9],        A22 = Ap[10] + 1.0f, A23 = Ap[11];

    int o = s / SPS;                  // warp-uniform orientation
    float tc = (float)(s % SPS) * ST_RATIO;
    int w = w0 + lane;
    int bb = b * HH * WW * ZV;

    // carry per c-corner: pixel p's u1-row awaiting merge with p+1's u0-row
    int   cLoA[2] = { -1, -1 };
    float cLoN[2], cLoD[2];
    int   cHiA[2];
    float cHiN[2], cHiD[2];
    bool  cHiS[2] = { false, false };

    for (int p = 0; p < CHAIN; p++) {
        int h = h0 + p;
        float v = sv[(p * 32 + lane) * 9 + wid];   // conflict-free (stride 9)

        float bx, by, bz;
        if (o == 0)      { bx = (float)h; by = (float)w; bz = tc; }
        else if (o == 1) { bx = (float)h; by = tc;       bz = (float)w; }
        else             { bx = tc;       by = (float)h; bz = (float)w; }

        float x = A00 * bx + A01 * by + A02 * bz + A03;
        float y = A10 * bx + A11 * by + A12 * bz + A13;
        float z = A20 * bx + A21 * by + A22 * bz + A23 + 1.0f;

        Axis U, V, C;
        if (o == 0) {
            U = axis_eval(x, HH, WW * ZV);
            V = axis_eval(y, WW, ZV);
            C = axis_eval(z, ZV, 1);
        } else if (o == 1) {
            U = axis_eval(x, HH, WW * ZV);
            V = axis_eval(z, ZV, 1);
            C = axis_eval(y, WW, ZV);
        } else {
            U = axis_eval(y, WW, ZV);
            V = axis_eval(z, ZV, 1);
            C = axis_eval(x, HH, WW * ZV);
        }

        // lo-row emission candidates per c (filled below, emitted after)
        int   eL[2];
        float eN[2], eD[2];

        #pragma unroll
        for (int c = 0; c < 2; c++) {
            int   ct = c ? C.t1 : C.t0;
            float fc = c ? C.f1 : C.f0;

            int   rL[2], rH[2];
            float rAccN[2], rAccD[2], rHiN[2], rHiD[2];
            bool  rS[2];

            // v-merge along the 32-lane w run, for both u rows
            #pragma unroll
            for (int r = 0; r < 2; r++) {
                int   ut = r ? U.t1 : U.t0;
                float fu = r ? U.f1 : U.f0;
                int L  = bb + ut + V.t0 + ct;
                int Hh = bb + ut + V.t1 + ct;
                float wlo = fu * V.f0 * fc;
                float whi = fu * V.f1 * fc;
                float NhiV = whi * v;

                float nbN = __shfl_up_sync(0xffffffffu, NhiV, 1);
                float nbD = __shfl_up_sync(0xffffffffu, whi, 1);
                int   nbH = __shfl_up_sync(0xffffffffu, Hh, 1);
                bool mrg = (lane > 0) && (nbH == L);
                unsigned bal = __ballot_sync(0xffffffffu, mrg);
                bool absorbed = (bal & (2u << lane)) != 0u;  // lane31 -> false

                rL[r]    = L;
                rAccN[r] = wlo * v + (mrg ? nbN : 0.0f);
                rAccD[r] = wlo     + (mrg ? nbD : 0.0f);
                rH[r]    = Hh;
                rHiN[r]  = NhiV;
                rHiD[r]  = whi;
                rS[r]    = !absorbed;
            }

            // u-chain: absorb previous pixel's u1-row (carry) into this u0-row
            if (cLoA[c] >= 0) {
                if (cLoA[c] == rL[0]) {
                    rAccN[0] += cLoN[c];
                    rAccD[0] += cLoD[c];
                } else {
                    red_add_v2(&g_acc[2 * cLoA[c]], cLoN[c], cLoD[c]);
                }
                if (cHiS[c]) {
                    if (rS[0] && cHiA[c] == rH[0]) {
                        rHiN[0] += cHiN[c];
                        rHiD[0] += cHiD[c];
                    } else {
                        red_add_v2(&g_acc[2 * cHiA[c]], cHiN[c], cHiD[c]);
                    }
                }
            }

            // record u0-row lo emission; emit surviving u0-row hi now (rare)
            eL[c] = rL[0]; eN[c] = rAccN[0]; eD[c] = rAccD[0];
            if (rS[0])
                red_add_v2(&g_acc[2 * rH[0]], rHiN[0], rHiD[0]);

            // u1-row becomes the new carry
            cLoA[c] = rL[1]; cLoN[c] = rAccN[1]; cLoD[c] = rAccD[1];
            cHiA[c] = rH[1]; cHiN[c] = rHiN[1]; cHiD[c] = rHiD[1];
            cHiS[c] = rS[1];
        }

        // emit the two lo-rows; axi fuses adjacent c-pairs into one v4 red
        if (o == 0) {
            bool fuse = (eL[1] == eL[0] + 1) && ((eL[0] & 1) == 0);
            if (fuse) {
                red_add_v4(&g_acc[2 * eL[0]], eN[0], eD[0], eN[1], eD[1]);
            } else {
                red_add_v2(&g_acc[2 * eL[0]], eN[0], eD[0]);
                red_add_v2(&g_acc[2 * eL[1]], eN[1], eD[1]);
            }
        } else {
            red_add_v2(&g_acc[2 * eL[0]], eN[0], eD[0]);
            red_add_v2(&g_acc[2 * eL[1]], eN[1], eD[1]);
        }
    }

    // flush remaining carries
    #pragma unroll
    for (int c = 0; c < 2; c++) {
        if (cLoA[c] >= 0) {
            red_add_v2(&g_acc[2 * cLoA[c]], cLoN[c], cLoD[c]);
            if (cHiS[c])
                red_add_v2(&g_acc[2 * cHiA[c]], cHiN[c], cHiD[c]);
        }
    }
}

// ---------------------------------------------------------------------------
// Finalize: crop z[1:1+ZS], split interleaved N/D, where(D<=0, 1, D).
// One warp per (b,h,w) column: strided passes of 32 z (last predicated).
// __ldcs on acc (dead after read; memset rewrites), __stcs on out (streaming,
// don't thrash the L2-resident accumulator).
// Grid = HWSZ*BB/8 = 8192 blocks of 256 (8 warps = 8 columns per block).
// ---------------------------------------------------------------------------
__global__ __launch_bounds__(256) void finalize_kernel(float* __restrict__ out)
{
    int lane = threadIdx.x & 31;
    int col  = blockIdx.x * 8 + (threadIdx.x >> 5);   // global hwb column

    const float2* acc = reinterpret_cast<const float2*>(g_acc);
    int lin = col * ZV + 1;
    int oj  = col * ZS;

    float2 p0 = __ldcs(&acc[lin + lane]);
    float2 p1 = __ldcs(&acc[lin + lane + 32]);
    float2 p2 = __ldcs(&acc[lin + lane + 64]);
    float2 p3 = (lane < 24) ? __ldcs(&acc[lin + lane + 96]) : make_float2(0.f, 0.f);

    __stcs(&out[oj + lane],      p0.x);
    __stcs(&out[oj + lane + 32], p1.x);
    __stcs(&out[oj + lane + 64], p2.x);
    __stcs(&out[OUT_PER + oj + lane],      (p0.y > 0.0f) ? p0.y : 1.0f);
    __stcs(&out[OUT_PER + oj + lane + 32], (p1.y > 0.0f) ? p1.y : 1.0f);
    __stcs(&out[OUT_PER + oj + lane + 64], (p2.y > 0.0f) ? p2.y : 1.0f);
    if (lane < 24) {
        __stcs(&out[oj + lane + 96],           p3.x);
        __stcs(&out[OUT_PER + oj + lane + 96], (p3.y > 0.0f) ? p3.y : 1.0f);
    }
}

// ---------------------------------------------------------------------------
extern "C" void kernel_launch(void* const* d_in, const int* in_sizes, int n_in,
                              void* d_out, int out_size)
{
    const float* vol = (const float*)d_in[0];
    const float* trf = (const float*)d_in[1];
    float* out = (float*)d_out;

    splat_kernel<<<BB * 9 * (HH / CHAIN) * 4, 256>>>(vol, trf);
    finalize_kernel<<<(HWSZ * BB) / 8, 256>>>(out);

    // Restore the all-zero invariant for the next replay; also leaves the
    // accumulator zeroed and warm in L2 for the next splat.
    void* acc_ptr = nullptr;
    cudaGetSymbolAddress(&acc_ptr, g_acc);
    cudaMemsetAsync(acc_ptr, 0, sizeof(float) * 2 * VOXELS, 0);
}

// round 12
// speedup vs baseline: 2.2521x; 1.0031x over previous
#include <cuda_runtime.h>
#include <cstdint>

// ---- problem constants (match reference) ----
#define BB 4
#define HH 128
#define WW 128
#define SS 72
#define SPS 24          // slices per stack
#define ZS 120          // z_scale
#define ZV 122          // padded depth
#define ST_RATIO 5.0f

#define VOXELS (BB * HH * WW * ZV)      // 7,995,392
#define PIXELS (BB * HH * WW * SS)      // 4,718,592
#define OUT_PER (BB * HH * WW * ZS)     // 7,864,320
#define HWSZ   (HH * WW)                // 16384

#define CHAIN 16                         // h-pixels per thread (u-chain length)

// Interleaved scratch: [2*lin]=N, [2*lin+1]=D. 64 MB, L2-resident.
// Tail cudaMemsetAsync restores the all-zero invariant after every execution.
__device__ __align__(16) float g_acc[2 * VOXELS];

__device__ __forceinline__ void red_add_v2(float* p, float a, float b) {
    asm volatile("red.global.add.v2.f32 [%0], {%1, %2};"
                 :: "l"(p), "f"(a), "f"(b) : "memory");
}

__device__ __forceinline__ void red_add_v4(float* p, float a, float b,
                                           float c, float d) {
    asm volatile("red.global.add.v4.f32 [%0], {%1, %2, %3, %4};"
                 :: "l"(p), "f"(a), "f"(b), "f"(c), "f"(d) : "memory");
}

// Per-axis corner terms: clipped address contributions + masked weights.
struct Axis { int t0, t1; float f0, f1; };

__device__ __forceinline__ Axis axis_eval(float q, int E, int St) {
    float qf = floorf(q);
    int q0 = (int)qf;
    float fr = q - qf;
    int i0 = min(max(q0, 0), E - 1);
    int i1 = min(max(q0 + 1, 0), E - 1);
    Axis a;
    a.t0 = i0 * St;
    a.t1 = i1 * St;
    a.f0 = (q0 >= 0 && q0 < E)      ? (1.0f - fr) : 0.0f;
    a.f1 = (q0 >= -1 && q0 < E - 1) ? fr          : 0.0f;
    return a;
}

// ---------------------------------------------------------------------------
// Splat. Warp = 32 lanes spanning full w (v-merge runs of 32). Each thread
// serially processes a chain of CHAIN h-pixels (u-axis), carrying the u1-row
// of pixel p in registers and merging it into pixel p+1's u0-row on exact
// address equality (sum-preserving; no extra warp communication).
// Axis roles per orientation:
//   axi: u=x(h, stride W*ZV)  v=y(w, stride ZV)  c=z(stride 1)
//   cor: u=x(h, stride W*ZV)  v=z(w, stride 1)   c=y(stride ZV)
//   sag: u=y(h, stride ZV)    v=z(w, stride 1)   c=x(stride W*ZV)
// For axi (c stride 1), the per-pixel lo-row emissions for the two c-corners
// hit consecutive N/D pairs; when 16B-aligned and truly adjacent they fuse
// into a single red.global.add.v4.f32.
// Block = 8 warps = 8 slices for the same (b, CHAIN-h chunk, 32-w chunk).
// Grid = B * 9(sc) * (128/CHAIN)(hc) * 4(wc) = 1152 blocks of 256.
// ---------------------------------------------------------------------------
__global__ __launch_bounds__(256) void splat_kernel(
    const float* __restrict__ vol,    // (B,H,W,S,1)
    const float* __restrict__ trf)    // (B,S,3,4)
{
    __shared__ float sv[CHAIN * 32 * 9];  // [ (h_local*32 + w_local)*9 + s_local ]

    int tid  = threadIdx.x;
    int lane = tid & 31;
    int wid  = tid >> 5;
    int blk  = blockIdx.x;

    int wc = blk & 3;
    int tt = blk >> 2;
    int hc = tt & 7;   tt >>= 3;       // 128/CHAIN = 8 h-chunks
    int sc = tt % 9;
    int b  = tt / 9;

    int h0 = hc * CHAIN, w0 = wc * 32;
    int s  = sc * 8 + wid;            // warp-uniform

    // Stage vol[b, h0..h0+CHAIN-1, w0..w0+31, sc*8..+7] into smem (coalesced,
    // sector-efficient; pad-9 rows for conflict-free readback).
    {
        const float* base = vol + (((size_t)(b * HH + h0) * WW + w0) * SS + sc * 8);
        #pragma unroll
        for (int it = 0; it < CHAIN; it++) {
            int idx = it * 256 + tid;
            int hh = idx >> 8;
            int wl = (idx >> 3) & 31;
            int sl = idx & 7;
            sv[(hh * 32 + wl) * 9 + sl] = base[((size_t)hh * WW + wl) * SS + sl];
        }
    }
    __syncthreads();

    const float* Ap = trf + (size_t)(b * SS + s) * 12;
    float A00 = Ap[0] + 1.0f, A01 = Ap[1],        A02 = Ap[2],         A03 = Ap[3];
    float A10 = Ap[4],        A11 = Ap[5] + 1.0f, A12 = Ap[6],         A13 = Ap[7];
    float A20 = Ap[8],        A21 = Ap[9],        A22 = Ap[10] + 1.0f, A23 = Ap[11];

    int o = s / SPS;                  // warp-uniform orientation
    float tc = (float)(s % SPS) * ST_RATIO;
    int w = w0 + lane;
    int bb = b * HH * WW * ZV;

    // carry per c-corner: pixel p's u1-row awaiting merge with p+1's u0-row
    int   cLoA[2] = { -1, -1 };
    float cLoN[2], cLoD[2];
    int   cHiA[2];
    float cHiN[2], cHiD[2];
    bool  cHiS[2] = { false, false };

    for (int p = 0; p < CHAIN; p++) {
        int h = h0 + p;
        float v = sv[(p * 32 + lane) * 9 + wid];   // conflict-free (stride 9)

        float bx, by, bz;
        if (o == 0)      { bx = (float)h; by = (float)w; bz = tc; }
        else if (o == 1) { bx = (float)h; by = tc;       bz = (float)w; }
        else             { bx = tc;       by = (float)h; bz = (float)w; }

        float x = A00 * bx + A01 * by + A02 * bz + A03;
        float y = A10 * bx + A11 * by + A12 * bz + A13;
        float z = A20 * bx + A21 * by + A22 * bz + A23 + 1.0f;

        Axis U, V, C;
        if (o == 0) {
            U = axis_eval(x, HH, WW * ZV);
            V = axis_eval(y, WW, ZV);
            C = axis_eval(z, ZV, 1);
        } else if (o == 1) {
            U = axis_eval(x, HH, WW * ZV);
            V = axis_eval(z, ZV, 1);
            C = axis_eval(y, WW, ZV);
        } else {
            U = axis_eval(y, WW, ZV);
            V = axis_eval(z, ZV, 1);
            C = axis_eval(x, HH, WW * ZV);
        }

        // lo-row emission candidates per c (filled below, emitted after)
        int   eL[2];
        float eN[2], eD[2];

        #pragma unroll
        for (int c = 0; c < 2; c++) {
            int   ct = c ? C.t1 : C.t0;
            float fc = c ? C.f1 : C.f0;

            int   rL[2], rH[2];
            float rAccN[2], rAccD[2], rHiN[2], rHiD[2];
            bool  rS[2];

            // v-merge along the 32-lane w run, for both u rows
            #pragma unroll
            for (int r = 0; r < 2; r++) {
                int   ut = r ? U.t1 : U.t0;
                float fu = r ? U.f1 : U.f0;
                int L  = bb + ut + V.t0 + ct;
                int Hh = bb + ut + V.t1 + ct;
                float wlo = fu * V.f0 * fc;
                float whi = fu * V.f1 * fc;
                float NhiV = whi * v;

                float nbN = __shfl_up_sync(0xffffffffu, NhiV, 1);
                float nbD = __shfl_up_sync(0xffffffffu, whi, 1);
                int   nbH = __shfl_up_sync(0xffffffffu, Hh, 1);
                bool mrg = (lane > 0) && (nbH == L);
                unsigned bal = __ballot_sync(0xffffffffu, mrg);
                bool absorbed = (bal & (2u << lane)) != 0u;  // lane31 -> false

                rL[r]    = L;
                rAccN[r] = wlo * v + (mrg ? nbN : 0.0f);
                rAccD[r] = wlo     + (mrg ? nbD : 0.0f);
                rH[r]    = Hh;
                rHiN[r]  = NhiV;
                rHiD[r]  = whi;
                rS[r]    = !absorbed;
            }

            // u-chain: absorb previous pixel's u1-row (carry) into this u0-row
            if (cLoA[c] >= 0) {
                if (cLoA[c] == rL[0]) {
                    rAccN[0] += cLoN[c];
                    rAccD[0] += cLoD[c];
                } else {
                    red_add_v2(&g_acc[2 * cLoA[c]], cLoN[c], cLoD[c]);
                }
                if (cHiS[c]) {
                    if (rS[0] && cHiA[c] == rH[0]) {
                        rHiN[0] += cHiN[c];
                        rHiD[0] += cHiD[c];
                    } else {
                        red_add_v2(&g_acc[2 * cHiA[c]], cHiN[c], cHiD[c]);
                    }
                }
            }

            // record u0-row lo emission; emit surviving u0-row hi now (rare)
            eL[c] = rL[0]; eN[c] = rAccN[0]; eD[c] = rAccD[0];
            if (rS[0])
                red_add_v2(&g_acc[2 * rH[0]], rHiN[0], rHiD[0]);

            // u1-row becomes the new carry
            cLoA[c] = rL[1]; cLoN[c] = rAccN[1]; cLoD[c] = rAccD[1];
            cHiA[c] = rH[1]; cHiN[c] = rHiN[1]; cHiD[c] = rHiD[1];
            cHiS[c] = rS[1];
        }

        // emit the two lo-rows; axi fuses adjacent c-pairs into one v4 red
        if (o == 0) {
            bool fuse = (eL[1] == eL[0] + 1) && ((eL[0] & 1) == 0);
            if (fuse) {
                red_add_v4(&g_acc[2 * eL[0]], eN[0], eD[0], eN[1], eD[1]);
            } else {
                red_add_v2(&g_acc[2 * eL[0]], eN[0], eD[0]);
                red_add_v2(&g_acc[2 * eL[1]], eN[1], eD[1]);
            }
        } else {
            red_add_v2(&g_acc[2 * eL[0]], eN[0], eD[0]);
            red_add_v2(&g_acc[2 * eL[1]], eN[1], eD[1]);
        }
    }

    // flush remaining carries
    #pragma unroll
    for (int c = 0; c < 2; c++) {
        if (cLoA[c] >= 0) {
            red_add_v2(&g_acc[2 * cLoA[c]], cLoN[c], cLoD[c]);
            if (cHiS[c])
                red_add_v2(&g_acc[2 * cHiA[c]], cHiN[c], cHiD[c]);
        }
    }
}

// ---------------------------------------------------------------------------
// Finalize: crop z[1:1+ZS], split interleaved N/D, where(D<=0, 1, D).
// One warp per (b,h,w) column: strided passes of 32 z (last predicated).
// __ldcs on acc (dead after read; memset rewrites), __stcs on out (streaming,
// don't thrash the L2-resident accumulator).
// Grid = HWSZ*BB/8 = 8192 blocks of 256 (8 warps = 8 columns per block).
// ---------------------------------------------------------------------------
__global__ __launch_bounds__(256) void finalize_kernel(float* __restrict__ out)
{
    int lane = threadIdx.x & 31;
    int col  = blockIdx.x * 8 + (threadIdx.x >> 5);   // global hwb column

    const float2* acc = reinterpret_cast<const float2*>(g_acc);
    int lin = col * ZV + 1;
    int oj  = col * ZS;

    float2 p0 = __ldcs(&acc[lin + lane]);
    float2 p1 = __ldcs(&acc[lin + lane + 32]);
    float2 p2 = __ldcs(&acc[lin + lane + 64]);
    float2 p3 = (lane < 24) ? __ldcs(&acc[lin + lane + 96]) : make_float2(0.f, 0.f);

    __stcs(&out[oj + lane],      p0.x);
    __stcs(&out[oj + lane + 32], p1.x);
    __stcs(&out[oj + lane + 64], p2.x);
    __stcs(&out[OUT_PER + oj + lane],      (p0.y > 0.0f) ? p0.y : 1.0f);
    __stcs(&out[OUT_PER + oj + lane + 32], (p1.y > 0.0f) ? p1.y : 1.0f);
    __stcs(&out[OUT_PER + oj + lane + 64], (p2.y > 0.0f) ? p2.y : 1.0f);
    if (lane < 24) {
        __stcs(&out[oj + lane + 96],           p3.x);
        __stcs(&out[OUT_PER + oj + lane + 96], (p3.y > 0.0f) ? p3.y : 1.0f);
    }
}

// ---------------------------------------------------------------------------
extern "C" void kernel_launch(void* const* d_in, const int* in_sizes, int n_in,
                              void* d_out, int out_size)
{
    const float* vol = (const float*)d_in[0];
    const float* trf = (const float*)d_in[1];
    float* out = (float*)d_out;

    splat_kernel<<<BB * 9 * (HH / CHAIN) * 4, 256>>>(vol, trf);
    finalize_kernel<<<(HWSZ * BB) / 8, 256>>>(out);

    // Restore the all-zero invariant for the next replay; also leaves the
    // accumulator zeroed and warm in L2 for the next splat.
    void* acc_ptr = nullptr;
    cudaGetSymbolAddress(&acc_ptr, g_acc);
    cudaMemsetAsync(acc_ptr, 0, sizeof(float) * 2 * VOXELS, 0);
}